// round 9
// baseline (speedup 1.0000x reference)
#include <cuda_runtime.h>

#define NN 128
#define PITCH 132          // rows 16B-aligned -> float4 row ops
#define ROWB (PITCH*4)     // 528 bytes per row
#define NB 8               // panel width; 16 panels
#define THREADS 256
#define SMEM_FLOATS (NN*PITCH + 8*NN)
#define SMEM_BYTES (SMEM_FLOATS * sizeof(float))

#define BAR_ARRIVE(id,n) asm volatile("bar.arrive %0, %1;" :: "r"(id), "r"(n) : "memory")
#define BAR_WAIT(id,n)   asm volatile("bar.sync %0, %1;"   :: "r"(id), "r"(n) : "memory")

// ---- warp-0 register panel factorization (pivot-flag, no swaps) ----
__device__ __forceinline__ void factor_panel(
    float (&pn)[4][NB], unsigned &act,
    float* __restrict__ A, float* __restrict__ spiv,
    int* __restrict__ listb, int* __restrict__ pivrowb,
    int* __restrict__ nactb, const int kbn, const int lane)
{
    const unsigned FULL = 0xFFFFFFFFu;
    #pragma unroll
    for (int kk = 0; kk < NB; ++kk) {
        // two parallel reductions: exact |v| (for rcp) and masked|idx (for pivot)
        unsigned keyv = 0u, keyi = 0u;
        #pragma unroll
        for (int s2 = 0; s2 < 4; ++s2)
            if ((act >> s2) & 1u) {
                const unsigned bb = __float_as_uint(fabsf(pn[s2][kk]));
                keyv = keyv > bb ? keyv : bb;
                const unsigned kv = (bb & 0xFFFFFF80u) | (unsigned)(lane + 32 * s2);
                keyi = keyi > kv ? keyi : kv;
            }
        const unsigned mv = __reduce_max_sync(FULL, keyv);
        const unsigned mi = __reduce_max_sync(FULL, keyi);
        const float rp_abs = __fdividef(1.0f, __uint_as_float(mv)); // starts early
        const int p = (int)(mi & 127u);
        const int plane = p & 31;
        const int pslot = p >> 5;

        float up[NB];
        #pragma unroll
        for (int j = kk; j < NB; ++j) {
            const float t = pslot == 0 ? pn[0][j]
                          : pslot == 1 ? pn[1][j]
                          : pslot == 2 ? pn[2][j] : pn[3][j];
            up[j] = __shfl_sync(FULL, t, plane);
        }
        const float rp_ = __uint_as_float(__float_as_uint(rp_abs)
                          ^ (__float_as_uint(up[kk]) & 0x80000000u));
        if (lane == plane) act &= ~(1u << pslot);
        if (lane == 0) { pivrowb[kk] = p; spiv[kbn + kk] = __uint_as_float(mv); }

        #pragma unroll
        for (int s2 = 0; s2 < 4; ++s2)
            if ((act >> s2) & 1u) {
                const float l = pn[s2][kk] * rp_;
                pn[s2][kk] = l;
                #pragma unroll
                for (int j = kk + 1; j < NB; ++j)
                    pn[s2][j] = fmaf(-l, up[j], pn[s2][j]);
            }
    }
    // write back panel
    #pragma unroll
    for (int s2 = 0; s2 < 4; ++s2) {
        float* row = A + (unsigned)(lane + 32 * s2) * PITCH + kbn;
        *(float4*)row =
            make_float4(pn[s2][0], pn[s2][1], pn[s2][2], pn[s2][3]);
        *(float4*)(row + 4) =
            make_float4(pn[s2][4], pn[s2][5], pn[s2][6], pn[s2][7]);
    }
    // ballot-compact active-row list (byte offsets)
    int base = 0;
    #pragma unroll
    for (int s2 = 0; s2 < 4; ++s2) {
        const unsigned am = __ballot_sync(FULL, (act >> s2) & 1u);
        const int pos = base + __popc(am & ((1u << lane) - 1u));
        if ((act >> s2) & 1u) listb[pos] = (lane + 32 * s2) * ROWB;
        base += __popc(am);
    }
    if (lane == 0) *nactb = base;
}

__device__ __forceinline__ void row_update(
    float* __restrict__ Arow, const int kb, const int q, const float4 (&u)[NB])
{
    const float4 l0 = *(const float4*)(Arow + kb);
    const float4 l1 = *(const float4*)(Arow + kb + 4);
    float4 a = *(float4*)(Arow + 4 * q);
    const float lm[NB] = {l0.x, l0.y, l0.z, l0.w, l1.x, l1.y, l1.z, l1.w};
    #pragma unroll
    for (int m = 0; m < NB; ++m) {
        a.x = fmaf(-lm[m], u[m].x, a.x);
        a.y = fmaf(-lm[m], u[m].y, a.y);
        a.z = fmaf(-lm[m], u[m].z, a.z);
        a.w = fmaf(-lm[m], u[m].w, a.w);
    }
    *(float4*)(Arow + 4 * q) = a;
}

__global__ void __launch_bounds__(THREADS, 3)
lsd_kernel(const float* __restrict__ rs,
           const float* __restrict__ kp,
           const float* __restrict__ cw,
           const float* __restrict__ sw,
           float* __restrict__ out)
{
    extern __shared__ float smem[];
    float* A   = smem;                 // NN * PITCH
    float* kx  = smem + NN * PITCH;    // build only
    float* ky  = kx + NN;
    float* kz  = ky + NN;
    float* scw = kz + NN;
    float* ssw = scw + NN;
    float* sr  = ssw + NN;             // 3*NN, build only
    // aliases after build:
    float* spiv  = kx;                 // NN pivots (abs values)
    int*   list0 = (int*)ky;           // active lists (double-buffered, byte offs)
    int*   list1 = (int*)kz;

    __shared__ int s_pivrow[2][NB];
    __shared__ int s_nact[2];
    __shared__ float s_part[4];

    const int tid = threadIdx.x;
    const int b = blockIdx.x;
    const unsigned FULL = 0xFFFFFFFFu;
    const int lane = tid & 31;
    const int wid = tid >> 5;

    if (tid < NN) {
        kx[tid]  = kp[3 * tid + 0];
        ky[tid]  = kp[3 * tid + 1];
        kz[tid]  = kp[3 * tid + 2];
        scw[tid] = cw[tid];
        ssw[tid] = sw[tid];
    }
    const float* rsb = rs + (size_t)b * (3 * NN);
    for (int t = tid; t < 3 * NN; t += THREADS) sr[t] = rsb[t];
    __syncthreads();

    // Build Slater matrix: A[i][m] = cw[m]*cos(k_m.r_i) - sw[m]*sin(k_m.r_i)
    for (int idx = tid; idx < NN * NN; idx += THREADS) {
        const int i = idx >> 7;
        const int m = idx & 127;
        float d = fmaf(sr[3 * i], kx[m],
                  fmaf(sr[3 * i + 1], ky[m], sr[3 * i + 2] * kz[m]));
        float s, c;
        __sincosf(d, &s, &c);
        A[i * PITCH + m] = scw[m] * c - ssw[m] * s;
    }
    __syncthreads();

    unsigned act = 0xFu;   // warp-0 active-row mask

    // ---- prologue: factor panel 0 (warp 0, registers) ----
    if (tid < 32) {
        float pn[4][NB];
        #pragma unroll
        for (int s2 = 0; s2 < 4; ++s2) {
            const float* row = A + (unsigned)(lane + 32 * s2) * PITCH;
            const float4 a0 = *(const float4*)row;
            const float4 a1 = *(const float4*)(row + 4);
            pn[s2][0]=a0.x; pn[s2][1]=a0.y; pn[s2][2]=a0.z; pn[s2][3]=a0.w;
            pn[s2][4]=a1.x; pn[s2][5]=a1.y; pn[s2][6]=a1.z; pn[s2][7]=a1.w;
        }
        factor_panel(pn, act, A, spiv, list0, s_pivrow[0], &s_nact[0], 0, lane);
    }
    __syncthreads();

    // ---- pipelined main loop: one __syncthreads per step ----
    for (int kb = 0; kb + NB < NN; kb += NB) {
        const int pb = (kb >> 3) & 1;
        int* listpb = pb ? list1 : list0;
        int* listnb = pb ? list0 : list1;
        const int kbn = kb + NB;
        const int qs = kbn >> 2;       // first quad (next-panel cols)
        const int nq = 32 - qs;        // quads incl 2 lookahead quads
        const int nqm = nq - 2;        // main quads

        if (wid == 0) {
            BAR_WAIT(1, 256);          // wait for lookahead-quad completion
            float pn[4][NB];
            #pragma unroll
            for (int s2 = 0; s2 < 4; ++s2) {
                const float* row = A + (unsigned)(lane + 32 * s2) * PITCH + kbn;
                const float4 a0 = *(const float4*)row;
                const float4 a1 = *(const float4*)(row + 4);
                pn[s2][0]=a0.x; pn[s2][1]=a0.y; pn[s2][2]=a0.z; pn[s2][3]=a0.w;
                pn[s2][4]=a1.x; pn[s2][5]=a1.y; pn[s2][6]=a1.z; pn[s2][7]=a1.w;
            }
            factor_panel(pn, act, A, spiv, listnb,
                         s_pivrow[pb ^ 1], &s_nact[pb ^ 1], kbn, lane);
        } else {
            const int nact = s_nact[pb];
            const int* prow = s_pivrow[pb];

            // === merged U12 prep: quads [qs,32), lane -> quad qs+lane ===
            float4 u[NB];
            {
                const int q = qs + (lane < nq ? lane : 0);
                #pragma unroll
                for (int m = 0; m < NB; ++m)
                    u[m] = *(const float4*)(A + prow[m] * PITCH + 4 * q);
                #pragma unroll
                for (int m = 1; m < NB; ++m) {
                    #pragma unroll
                    for (int n = 0; n < m; ++n) {
                        const float l11 = A[prow[m] * PITCH + kb + n]; // bcast
                        u[m].x = fmaf(-l11, u[n].x, u[m].x);
                        u[m].y = fmaf(-l11, u[n].y, u[m].y);
                        u[m].z = fmaf(-l11, u[n].z, u[m].z);
                        u[m].w = fmaf(-l11, u[n].w, u[m].w);
                    }
                }
            }

            // === lookahead: next-panel cols kbn..kbn+7, float2 per lane ===
            {
                const int rsub = lane >> 2;        // 8 rows per warp-iter
                const int half = lane & 3;         // quad = half>>1, pair = half&1
                const int srcl = half >> 1;
                const int pair = half & 1;
                float u2x[NB], u2y[NB];
                #pragma unroll
                for (int m = 0; m < NB; ++m) {
                    const float sx = __shfl_sync(FULL, u[m].x, srcl);
                    const float sy = __shfl_sync(FULL, u[m].y, srcl);
                    const float sz = __shfl_sync(FULL, u[m].z, srcl);
                    const float sw2 = __shfl_sync(FULL, u[m].w, srcl);
                    u2x[m] = pair ? sz : sx;
                    u2y[m] = pair ? sw2 : sy;
                }
                const int cofs = kbn + (half << 1);
                for (int idx = (wid - 1) * 8 + rsub; idx < nact; idx += 56) {
                    float* Arow = (float*)((char*)A + listpb[idx]);
                    const float4 l0 = *(const float4*)(Arow + kb);
                    const float4 l1 = *(const float4*)(Arow + kb + 4);
                    float2 a = *(float2*)(Arow + cofs);
                    const float lm[NB] = {l0.x, l0.y, l0.z, l0.w,
                                          l1.x, l1.y, l1.z, l1.w};
                    #pragma unroll
                    for (int m = 0; m < NB; ++m) {
                        a.x = fmaf(-lm[m], u2x[m], a.x);
                        a.y = fmaf(-lm[m], u2y[m], a.y);
                    }
                    *(float2*)(Arow + cofs) = a;
                }
                __threadfence_block();
                BAR_ARRIVE(1, 256);
            }

            // === main GEMM: cols [kbn+8, NN), overlapped with warp-0 factor ===
            if (nqm > 8) {
                // lane = quad (lanes 2..nq-1), 1 row per warp-iter
                if (lane >= 2 && lane < nq) {
                    const int q = qs + lane;
                    for (int idx = wid - 1; idx < nact; idx += 7)
                        row_update((float*)((char*)A + listpb[idx]), kb, q, u);
                }
            } else if (nqm > 0) {
                // small trailing block: rp rows x nqm quads per warp-iter
                const int rp = 32 / nqm;
                const int sub = lane / nqm;
                const int qi = lane - sub * nqm;
                float4 ur[NB];
                #pragma unroll
                for (int m = 0; m < NB; ++m) {       // all lanes participate
                    ur[m].x = __shfl_sync(FULL, u[m].x, 2 + qi);
                    ur[m].y = __shfl_sync(FULL, u[m].y, 2 + qi);
                    ur[m].z = __shfl_sync(FULL, u[m].z, 2 + qi);
                    ur[m].w = __shfl_sync(FULL, u[m].w, 2 + qi);
                }
                if (sub < rp) {
                    const int q = qs + 2 + qi;
                    for (int idx = (wid - 1) * rp + sub; idx < nact; idx += 7 * rp)
                        row_update((float*)((char*)A + listpb[idx]), kb, q, ur);
                }
            }
        }
        __syncthreads();
    }

    // ---- log|det| = sum log(|piv|) ----
    float lv = 0.0f;
    if (tid < NN) lv = __logf(spiv[tid]);   // spiv stores |pivot|
    #pragma unroll
    for (int o = 16; o > 0; o >>= 1)
        lv += __shfl_xor_sync(FULL, lv, o);
    if (tid < NN && (tid & 31) == 0) s_part[tid >> 5] = lv;
    __syncthreads();
    if (tid == 0)
        out[b] = s_part[0] + s_part[1] + s_part[2] + s_part[3];
}

extern "C" void kernel_launch(void* const* d_in, const int* in_sizes, int n_in,
                              void* d_out, int out_size)
{
    const float* rs = (const float*)d_in[0];
    const float* kp = (const float*)d_in[1];
    const float* cw = (const float*)d_in[2];
    const float* sw = (const float*)d_in[3];
    float* out = (float*)d_out;

    const int batch = in_sizes[0] / (3 * NN);

    cudaFuncSetAttribute(lsd_kernel,
                         cudaFuncAttributeMaxDynamicSharedMemorySize,
                         (int)SMEM_BYTES);

    lsd_kernel<<<batch, THREADS, SMEM_BYTES>>>(rs, kp, cw, sw, out);
}

// round 10
// speedup vs baseline: 1.0264x; 1.0264x over previous
#include <cuda_runtime.h>

#define NN 128
#define PITCH 132          // rows 16B-aligned -> float4/ulonglong2 row ops
#define ROWB (PITCH*4)     // 528 bytes per row
#define NB 8               // panel width; 16 panels
#define THREADS 256
#define SMEM_FLOATS (NN*PITCH + 8*NN)
#define SMEM_BYTES (SMEM_FLOATS * sizeof(float))

#define BAR_ARRIVE(id,n) asm volatile("bar.arrive %0, %1;" :: "r"(id), "r"(n) : "memory")
#define BAR_WAIT(id,n)   asm volatile("bar.sync %0, %1;"   :: "r"(id), "r"(n) : "memory")

typedef unsigned long long ull;

__device__ __forceinline__ ull dup2f(float x) {
    ull r; unsigned b = __float_as_uint(x);
    asm("mov.b64 %0, {%1, %1};" : "=l"(r) : "r"(b));
    return r;
}
__device__ __forceinline__ ull fma2(ull a, ull b, ull c) {
    ull d;
    asm("fma.rn.f32x2 %0, %1, %2, %3;" : "=l"(d) : "l"(a), "l"(b), "l"(c));
    return d;
}

// ---- warp-0 register panel factorization; stores NEGATED L multipliers ----
__device__ __forceinline__ void factor_panel(
    float (&pn)[4][NB], unsigned &act,
    float* __restrict__ A, float* __restrict__ spiv,
    int* __restrict__ listb, int* __restrict__ pivrowb,
    int* __restrict__ nactb, const int kbn, const int lane)
{
    const unsigned FULL = 0xFFFFFFFFu;
    #pragma unroll
    for (int kk = 0; kk < NB; ++kk) {
        unsigned key = 0u;
        #pragma unroll
        for (int s2 = 0; s2 < 4; ++s2)
            if ((act >> s2) & 1u) {
                const unsigned kv =
                    (__float_as_uint(fabsf(pn[s2][kk])) & 0xFFFFFF80u)
                    | (unsigned)(lane + 32 * s2);
                key = key > kv ? key : kv;
            }
        const unsigned mm = __reduce_max_sync(FULL, key);
        const int p = (int)(mm & 127u);
        const int plane = p & 31;
        const int pslot = p >> 5;

        float up[NB];
        #pragma unroll
        for (int j = kk; j < NB; ++j) {
            const float t = pslot == 0 ? pn[0][j]
                          : pslot == 1 ? pn[1][j]
                          : pslot == 2 ? pn[2][j] : pn[3][j];
            up[j] = __shfl_sync(FULL, t, plane);
        }
        const float pv = up[kk];
        const float rpn = __fdividef(-1.0f, pv);   // NEGATED reciprocal
        if (lane == plane) act &= ~(1u << pslot);
        if (lane == 0) { pivrowb[kk] = p; spiv[kbn + kk] = pv; }

        #pragma unroll
        for (int s2 = 0; s2 < 4; ++s2)
            if ((act >> s2) & 1u) {
                const float l = pn[s2][kk] * rpn;  // l = -L_true
                pn[s2][kk] = l;
                #pragma unroll
                for (int j = kk + 1; j < NB; ++j)
                    pn[s2][j] = fmaf(l, up[j], pn[s2][j]);
            }
    }
    // write back panel (negated L + pivot-row values)
    #pragma unroll
    for (int s2 = 0; s2 < 4; ++s2) {
        float* row = A + (unsigned)(lane + 32 * s2) * PITCH + kbn;
        *(float4*)row =
            make_float4(pn[s2][0], pn[s2][1], pn[s2][2], pn[s2][3]);
        *(float4*)(row + 4) =
            make_float4(pn[s2][4], pn[s2][5], pn[s2][6], pn[s2][7]);
    }
    // ballot-compact active-row list (byte offsets)
    int base = 0;
    #pragma unroll
    for (int s2 = 0; s2 < 4; ++s2) {
        const unsigned am = __ballot_sync(FULL, (act >> s2) & 1u);
        const int pos = base + __popc(am & ((1u << lane) - 1u));
        if ((act >> s2) & 1u) listb[pos] = (lane + 32 * s2) * ROWB;
        base += __popc(am);
    }
    if (lane == 0) *nactb = base;
}

// ---- warp-0: duplicate the (negated) L11 strictly-lower entries into b64 ----
__device__ __forceinline__ void dup_store_l11(
    const float* __restrict__ A, const int* __restrict__ pivrowb,
    ull* __restrict__ nlbuf, const int kbn, const int lane)
{
    __syncwarp();
    if (lane < 28) {
        const int m = (int)((1.0f + sqrtf(1.0f + 8.0f * (float)lane)) * 0.5f);
        const int n = lane - (m * (m - 1)) / 2;
        const float v = A[pivrowb[m] * PITCH + kbn + n];
        nlbuf[lane] = dup2f(v);
    }
}

// ---- load U12 quad (packed) and apply in-register TRSM via dup'd -L11 ----
__device__ __forceinline__ void load_u_trsm_p(
    ull (&u0)[NB], ull (&u1)[NB], const float* __restrict__ A,
    const int* __restrict__ prow, const ull* __restrict__ nl, const int q)
{
    #pragma unroll
    for (int m = 0; m < NB; ++m) {
        const ulonglong2 t = *(const ulonglong2*)(A + prow[m] * PITCH + 4 * q);
        u0[m] = t.x; u1[m] = t.y;
    }
    int idx = 0;
    #pragma unroll
    for (int m = 1; m < NB; ++m) {
        #pragma unroll
        for (int n = 0; n < m; ++n) {
            const ull c = nl[idx++];           // uniform -> broadcast LDS.64
            u0[m] = fma2(c, u0[n], u0[m]);
            u1[m] = fma2(c, u1[n], u1[m]);
        }
    }
}

__device__ __forceinline__ void row_update_p(
    float* __restrict__ Arow, const int kb, const int q,
    const ull (&u0)[NB], const ull (&u1)[NB])
{
    const float4 l0 = *(const float4*)(Arow + kb);   // negated L (broadcast)
    const float4 l1 = *(const float4*)(Arow + kb + 4);
    ulonglong2 a = *(ulonglong2*)(Arow + 4 * q);
    ull lm;
    lm = dup2f(l0.x); a.x = fma2(lm, u0[0], a.x); a.y = fma2(lm, u1[0], a.y);
    lm = dup2f(l0.y); a.x = fma2(lm, u0[1], a.x); a.y = fma2(lm, u1[1], a.y);
    lm = dup2f(l0.z); a.x = fma2(lm, u0[2], a.x); a.y = fma2(lm, u1[2], a.y);
    lm = dup2f(l0.w); a.x = fma2(lm, u0[3], a.x); a.y = fma2(lm, u1[3], a.y);
    lm = dup2f(l1.x); a.x = fma2(lm, u0[4], a.x); a.y = fma2(lm, u1[4], a.y);
    lm = dup2f(l1.y); a.x = fma2(lm, u0[5], a.x); a.y = fma2(lm, u1[5], a.y);
    lm = dup2f(l1.z); a.x = fma2(lm, u0[6], a.x); a.y = fma2(lm, u1[6], a.y);
    lm = dup2f(l1.w); a.x = fma2(lm, u0[7], a.x); a.y = fma2(lm, u1[7], a.y);
    *(ulonglong2*)(Arow + 4 * q) = a;
}

__global__ void __launch_bounds__(THREADS, 3)
lsd_kernel(const float* __restrict__ rs,
           const float* __restrict__ kp,
           const float* __restrict__ cw,
           const float* __restrict__ sw,
           float* __restrict__ out)
{
    extern __shared__ float smem[];
    float* A   = smem;                 // NN * PITCH
    float* kx  = smem + NN * PITCH;    // build only
    float* ky  = kx + NN;
    float* kz  = ky + NN;
    float* scw = kz + NN;
    float* ssw = scw + NN;
    float* sr  = ssw + NN;             // 3*NN, build only
    // aliases after build:
    float* spiv  = kx;                 // NN pivots
    int*   list0 = (int*)ky;           // active lists (byte offsets)
    int*   list1 = (int*)kz;

    __shared__ int s_pivrow[2][NB];
    __shared__ int s_nact[2];
    __shared__ float s_part[4];
    __shared__ ull s_nl11[2][28];      // duplicated negated L11 (double-buffered)

    const int tid = threadIdx.x;
    const int b = blockIdx.x;
    const unsigned FULL = 0xFFFFFFFFu;
    const int lane = tid & 31;
    const int wid = tid >> 5;

    if (tid < NN) {
        kx[tid]  = kp[3 * tid + 0];
        ky[tid]  = kp[3 * tid + 1];
        kz[tid]  = kp[3 * tid + 2];
        scw[tid] = cw[tid];
        ssw[tid] = sw[tid];
    }
    const float* rsb = rs + (size_t)b * (3 * NN);
    for (int t = tid; t < 3 * NN; t += THREADS) sr[t] = rsb[t];
    __syncthreads();

    // Build Slater matrix: A[i][m] = cw[m]*cos(k_m.r_i) - sw[m]*sin(k_m.r_i)
    for (int idx = tid; idx < NN * NN; idx += THREADS) {
        const int i = idx >> 7;
        const int m = idx & 127;
        float d = fmaf(sr[3 * i], kx[m],
                  fmaf(sr[3 * i + 1], ky[m], sr[3 * i + 2] * kz[m]));
        float s, c;
        __sincosf(d, &s, &c);
        A[i * PITCH + m] = scw[m] * c - ssw[m] * s;
    }
    __syncthreads();

    unsigned act = 0xFu;

    // ---- prologue: factor panel 0 (warp 0, registers) ----
    if (tid < 32) {
        float pn[4][NB];
        #pragma unroll
        for (int s2 = 0; s2 < 4; ++s2) {
            const float* row = A + (unsigned)(lane + 32 * s2) * PITCH;
            const float4 a0 = *(const float4*)row;
            const float4 a1 = *(const float4*)(row + 4);
            pn[s2][0]=a0.x; pn[s2][1]=a0.y; pn[s2][2]=a0.z; pn[s2][3]=a0.w;
            pn[s2][4]=a1.x; pn[s2][5]=a1.y; pn[s2][6]=a1.z; pn[s2][7]=a1.w;
        }
        factor_panel(pn, act, A, spiv, list0, s_pivrow[0], &s_nact[0], 0, lane);
        dup_store_l11(A, s_pivrow[0], s_nl11[0], 0, lane);
    }
    __syncthreads();

    // ---- pipelined main loop: one __syncthreads per step ----
    for (int kb = 0; kb + NB < NN; kb += NB) {
        const int pb = (kb >> 3) & 1;
        int* listpb = pb ? list1 : list0;
        int* listnb = pb ? list0 : list1;
        const int kbn = kb + NB;
        const int qs = kbn >> 2;       // first lookahead quad
        const int q0v = qs + 2;        // first main quad
        const int nqm = 30 - qs;       // main quad count

        if (wid == 0) {
            BAR_WAIT(1, 256);          // wait for lookahead quads
            float pn[4][NB];
            #pragma unroll
            for (int s2 = 0; s2 < 4; ++s2) {
                const float* row = A + (unsigned)(lane + 32 * s2) * PITCH + kbn;
                const float4 a0 = *(const float4*)row;
                const float4 a1 = *(const float4*)(row + 4);
                pn[s2][0]=a0.x; pn[s2][1]=a0.y; pn[s2][2]=a0.z; pn[s2][3]=a0.w;
                pn[s2][4]=a1.x; pn[s2][5]=a1.y; pn[s2][6]=a1.z; pn[s2][7]=a1.w;
            }
            factor_panel(pn, act, A, spiv, listnb,
                         s_pivrow[pb ^ 1], &s_nact[pb ^ 1], kbn, lane);
            dup_store_l11(A, s_pivrow[pb ^ 1], s_nl11[pb ^ 1], kbn, lane);
        } else {
            const int nact = s_nact[pb];
            const int* prow = s_pivrow[pb];
            const ull* nl = s_nl11[pb];
            ull u0[NB], u1[NB];

            // --- lookahead: 2 quads of next panel, 16 rows per warp-iter ---
            {
                const int q = qs + (lane & 1);
                load_u_trsm_p(u0, u1, A, prow, nl, q);
                for (int idx = (wid - 1) * 16 + (lane >> 1); idx < nact; idx += 112)
                    row_update_p((float*)((char*)A + listpb[idx]), kb, q, u0, u1);
                __threadfence_block();
                BAR_ARRIVE(1, 256);
            }

            // --- main GEMM: cols [kbn+8, NN), overlapped with warp-0 factor ---
            if (nqm > 8) {
                const int q = q0v + (lane < nqm ? lane : 0);
                load_u_trsm_p(u0, u1, A, prow, nl, q);
                if (lane < nqm) {
                    for (int idx = wid - 1; idx < nact; idx += 7)
                        row_update_p((float*)((char*)A + listpb[idx]), kb, q, u0, u1);
                }
            } else if (nqm > 0) {
                // small trailing block: rp rows x nqm quads, all lanes busy
                const int q = q0v + (lane < nqm ? lane : 0);
                load_u_trsm_p(u0, u1, A, prow, nl, q);
                const int rp = 32 / nqm;
                const int sub = lane / nqm;
                const int qi = lane - sub * nqm;
                #pragma unroll
                for (int m = 0; m < NB; ++m) {    // in-place redistribution
                    u0[m] = __shfl_sync(FULL, u0[m], qi);
                    u1[m] = __shfl_sync(FULL, u1[m], qi);
                }
                if (sub < rp) {
                    const int qq = q0v + qi;
                    for (int idx = (wid - 1) * rp + sub; idx < nact; idx += 7 * rp)
                        row_update_p((float*)((char*)A + listpb[idx]), kb, qq, u0, u1);
                }
            }
        }
        __syncthreads();
    }

    // ---- log|det| = sum log|piv| ----
    float lv = 0.0f;
    if (tid < NN) lv = __logf(fabsf(spiv[tid]));
    #pragma unroll
    for (int o = 16; o > 0; o >>= 1)
        lv += __shfl_xor_sync(FULL, lv, o);
    if (tid < NN && (tid & 31) == 0) s_part[tid >> 5] = lv;
    __syncthreads();
    if (tid == 0)
        out[b] = s_part[0] + s_part[1] + s_part[2] + s_part[3];
}

extern "C" void kernel_launch(void* const* d_in, const int* in_sizes, int n_in,
                              void* d_out, int out_size)
{
    const float* rs = (const float*)d_in[0];
    const float* kp = (const float*)d_in[1];
    const float* cw = (const float*)d_in[2];
    const float* sw = (const float*)d_in[3];
    float* out = (float*)d_out;

    const int batch = in_sizes[0] / (3 * NN);

    cudaFuncSetAttribute(lsd_kernel,
                         cudaFuncAttributeMaxDynamicSharedMemorySize,
                         (int)SMEM_BYTES);

    lsd_kernel<<<batch, THREADS, SMEM_BYTES>>>(rs, kp, cw, sw, out);
}